// round 10
// baseline (speedup 1.0000x reference)
#include <cuda_runtime.h>

// out[b, i, p] = W[i, b] * params[p, b]
// params: [P=512, B=512] row-major; W: [I=512, B=512] row-major
// out:    [B=512, I=512, P=512] row-major. 536 MB pure streaming stores.
//
// Evidence so far: DRAM-write-bound at ~5.2-5.9 TB/s; occ=4/unroll-8 neutral
// (R6), so warp residency is not the limiter. This round: best config (occ=2,
// unroll 4) with DEFAULT stores instead of __stcs — test whether L2 write-back
// aggregation beats eager streaming eviction.

#define NDIM 512

__global__ __launch_bounds__(512, 2)
void outer_scale_kernel(const float* __restrict__ params,
                        const float* __restrict__ W,
                        float* __restrict__ out) {
    __shared__ float pcol[NDIM];
    __shared__ float wcol[NDIM];

    const int b = blockIdx.x;
    const int t = threadIdx.x;  // 512 threads

    // Stage column b (the only strided reads: 2 x 512 sectors per block)
    pcol[t] = __ldg(&params[t * NDIM + b]);
    wcol[t] = __ldg(&W[t * NDIM + b]);
    __syncthreads();

    float4* out4 = reinterpret_cast<float4*>(out) + (size_t)b * (NDIM * NDIM / 4);
    const float4* p4 = reinterpret_cast<const float4*>(pcol);

    // 65536 float4 per block; 128 iters/thread. Lanes within a warp hit
    // consecutive float4s (coalesced STG.128); wcol[i] is an LDS broadcast.
#pragma unroll 4
    for (int idx = t; idx < NDIM * (NDIM / 4); idx += 512) {
        const int i  = idx >> 7;        // row
        const float w = wcol[i];
        float4 v = p4[idx & 127];
        v.x *= w; v.y *= w; v.z *= w; v.w *= w;
        out4[idx] = v;                  // default store: let L2 aggregate writebacks
    }
}

extern "C" void kernel_launch(void* const* d_in, const int* in_sizes, int n_in,
                              void* d_out, int out_size) {
    const float* params = (const float*)d_in[0];
    const float* W      = (const float*)d_in[1];
    float* out          = (float*)d_out;

    outer_scale_kernel<<<NDIM, 512>>>(params, W, out);
}

// round 16
// speedup vs baseline: 1.0111x; 1.0111x over previous
#include <cuda_runtime.h>

// out[b, i, p] = W[i, b] * params[p, b]
// params: [P=512, B=512] row-major; W: [I=512, B=512] row-major
// out:    [B=512, I=512, P=512] row-major. 536 MB pure streaming stores.
//
// Measured: store-bound at ~5.3-5.9 TB/s (DRAM 65-67%, pipes idle).
//   __stcs/occ2/u4: 90.9us | __stcs/occ4/u8: 92.2us | default/occ2/u4: 92.3us
// This round: keep the best config, make the grid PERSISTENT (304 CTAs =
// 2/SM x 152 SMs, each loops over its b values) to remove the wave-2
// transition + 208 CTA re-launches. Per-b smem staging preserved.

#define NDIM 512
#define GRID 304   // 152 SMs x 2 CTAs (GB300); harmless if SM count differs

__global__ __launch_bounds__(512, 2)
void outer_scale_kernel(const float* __restrict__ params,
                        const float* __restrict__ W,
                        float* __restrict__ out) {
    __shared__ float pcol[NDIM];
    __shared__ float wcol[NDIM];

    const int t = threadIdx.x;  // 512 threads

    for (int b = blockIdx.x; b < NDIM; b += GRID) {
        // Stage column b (the only strided reads: 2 x 512 sectors per b)
        pcol[t] = __ldg(&params[t * NDIM + b]);
        wcol[t] = __ldg(&W[t * NDIM + b]);
        __syncthreads();

        float4* out4 = reinterpret_cast<float4*>(out) + (size_t)b * (NDIM * NDIM / 4);
        const float4* p4 = reinterpret_cast<const float4*>(pcol);

        // 65536 float4 per b; 128 iters/thread. Coalesced STG.128;
        // wcol[i] is an LDS broadcast within each warp.
#pragma unroll 4
        for (int idx = t; idx < NDIM * (NDIM / 4); idx += 512) {
            const int i  = idx >> 7;    // row
            const float w = wcol[i];
            float4 v = p4[idx & 127];
            v.x *= w; v.y *= w; v.z *= w; v.w *= w;
            __stcs(&out4[idx], v);      // streaming store: write-once data
        }
        __syncthreads();                // all reads of pcol/wcol done before restage
    }
}

extern "C" void kernel_launch(void* const* d_in, const int* in_sizes, int n_in,
                              void* d_out, int out_size) {
    const float* params = (const float*)d_in[0];
    const float* W      = (const float*)d_in[1];
    float* out          = (float*)d_out;

    outer_scale_kernel<<<GRID, 512>>>(params, W, out);
}